// round 2
// baseline (speedup 1.0000x reference)
#include <cuda_runtime.h>

#define BB 512
#define KK 800
#define DD 512
#define NPAD 1024          // bitonic sort size (next pow2 >= KK)
#define SPLIT 4            // chunks per batch row in the dot kernel

// Scratch: per-b sorted (idx, k) pairs packed as (idx << 10) | k.
__device__ unsigned long long g_sorted[(size_t)BB * KK];

// ---------------------------------------------------------------------------
// Kernel 1: per-b bitonic sort of the 800 shortlist indices (key = idx).
// One block per b. 1024-wide bitonic in shared, pad with +inf keys.
// ---------------------------------------------------------------------------
__global__ __launch_bounds__(256) void sort_kernel(const int* __restrict__ shortlist)
{
    __shared__ unsigned long long s[NPAD];
    const int b = blockIdx.x;

    for (int i = threadIdx.x; i < NPAD; i += blockDim.x) {
        if (i < KK) {
            unsigned long long idx =
                (unsigned long long)(unsigned int)shortlist[b * KK + i];
            s[i] = (idx << 10) | (unsigned long long)i;   // k in low 10 bits
        } else {
            s[i] = ~0ULL;
        }
    }
    __syncthreads();

    for (int k = 2; k <= NPAD; k <<= 1) {
        for (int j = k >> 1; j > 0; j >>= 1) {
            for (int t = threadIdx.x; t < NPAD; t += blockDim.x) {
                int ixj = t ^ j;
                if (ixj > t) {
                    unsigned long long a = s[t], c = s[ixj];
                    bool up = ((t & k) == 0);
                    if ((a > c) == up) { s[t] = c; s[ixj] = a; }
                }
            }
            __syncthreads();
        }
    }

    unsigned long long* dst = g_sorted + (size_t)b * KK;
    for (int i = threadIdx.x; i < KK; i += blockDim.x)
        dst[i] = s[i];
}

// ---------------------------------------------------------------------------
// Kernel 2: dot products in sorted-idx order.
// grid = (SPLIT, BB); block = 256 (8 warps). Embed row staged in shared.
// Warp per item, float4 loads, shuffle reduction.
// All concurrent blocks sweep idx-space monotonically -> duplicate weight
// rows land in a small moving L2 window -> DRAM traffic ~= unique rows only.
// ---------------------------------------------------------------------------
__global__ __launch_bounds__(256) void dot_kernel(
    const float* __restrict__ embed,
    const float* __restrict__ sp_weight,
    const float* __restrict__ sp_bias,
    float*       __restrict__ out)
{
    __shared__ float4 s_embed[DD / 4];

    const int b = blockIdx.y;
    const int chunk = blockIdx.x;

    const float4* erow = reinterpret_cast<const float4*>(embed + (size_t)b * DD);
    for (int i = threadIdx.x; i < DD / 4; i += blockDim.x)
        s_embed[i] = erow[i];
    __syncthreads();

    const int warp = threadIdx.x >> 5;
    const int lane = threadIdx.x & 31;

    const unsigned long long* items = g_sorted + (size_t)b * KK;
    const int per   = KK / SPLIT;            // 200
    const int begin = chunk * per;
    const int end   = begin + per;

    for (int j = begin + warp; j < end; j += 8) {
        const unsigned long long it = items[j];
        const int       k   = (int)(it & 1023u);
        const long long idx = (long long)(it >> 10);

        const float4* wrow =
            reinterpret_cast<const float4*>(sp_weight + idx * DD);

        float sum = 0.0f;
        #pragma unroll
        for (int i = 0; i < DD / 128; ++i) {   // 4 independent LDG.128
            float4 w = wrow[i * 32 + lane];
            float4 e = s_embed[i * 32 + lane];
            sum = fmaf(w.x, e.x, sum);
            sum = fmaf(w.y, e.y, sum);
            sum = fmaf(w.z, e.z, sum);
            sum = fmaf(w.w, e.w, sum);
        }

        #pragma unroll
        for (int off = 16; off; off >>= 1)
            sum += __shfl_xor_sync(0xffffffffu, sum, off);

        if (lane == 0)
            out[b * KK + k] = sum + __ldg(&sp_bias[idx]);
    }
}

extern "C" void kernel_launch(void* const* d_in, const int* in_sizes, int n_in,
                              void* d_out, int out_size) {
    const float* embed     = (const float*)d_in[0];
    const int*   shortlist = (const int*)  d_in[1];
    const float* sp_weight = (const float*)d_in[2];
    const float* sp_bias   = (const float*)d_in[3];
    float*       out       = (float*)d_out;

    sort_kernel<<<BB, 256>>>(shortlist);
    dot_kernel<<<dim3(SPLIT, BB), 256>>>(embed, sp_weight, sp_bias, out);
}

// round 3
// speedup vs baseline: 1.4134x; 1.4134x over previous
#include <cuda_runtime.h>

#define BB 512
#define KK 800
#define DD 512
#define LL 500000
#define NB 32
#define BSZ (LL / NB)          // 15625 rows per bucket, exact

// Scratch: per-b bucketed items packed as (idx << 10) | k  (idx<2^19, k<2^10)
__device__ unsigned int g_items[(size_t)BB * KK];
// Per-(b,bucket) start offsets; g_off[b][NB] = KK sentinel.
__device__ int g_off[BB * (NB + 1)];

// ---------------------------------------------------------------------------
// Kernel 1: per-b counting sort into NB idx-range buckets.
// One block per b: shared histogram -> warp scan -> scatter. ~3 passes of 800.
// ---------------------------------------------------------------------------
__global__ __launch_bounds__(256) void bucket_kernel(const int* __restrict__ shortlist)
{
    __shared__ int hist[NB];
    __shared__ int cursor[NB];
    __shared__ unsigned int s_items[KK];   // 3.2 KB

    const int b = blockIdx.x;
    const int t = threadIdx.x;

    if (t < NB) hist[t] = 0;
    __syncthreads();

    for (int i = t; i < KK; i += 256) {
        unsigned idx = (unsigned)shortlist[b * KK + i];
        s_items[i] = (idx << 10) | (unsigned)i;
        atomicAdd(&hist[idx / BSZ], 1);
    }
    __syncthreads();

    if (t < 32) {
        int h = hist[t];
        int v = h;
        #pragma unroll
        for (int o = 1; o < 32; o <<= 1) {            // inclusive warp scan
            int n = __shfl_up_sync(0xffffffffu, v, o);
            if (t >= o) v += n;
        }
        int excl = v - h;                             // exclusive
        cursor[t] = excl;
        g_off[b * (NB + 1) + t] = excl;
        if (t == 31) g_off[b * (NB + 1) + NB] = KK;
    }
    __syncthreads();

    for (int i = t; i < KK; i += 256) {
        unsigned it = s_items[i];
        int bucket = (int)((it >> 10) / BSZ);
        int pos = atomicAdd(&cursor[bucket], 1);
        g_items[(size_t)b * KK + pos] = it;
    }
}

// ---------------------------------------------------------------------------
// Kernel 2: dot products, grid = (b fast, bucket slow).
// Linear bid order => all ~1184 resident blocks share 2-3 idx buckets
// (~74 MB weight footprint < L2) => duplicate rows across b hit L2.
// Embed[b] staged in shared (read once per block).
// ---------------------------------------------------------------------------
__global__ __launch_bounds__(256) void dot_kernel(
    const float* __restrict__ embed,
    const float* __restrict__ sp_weight,
    const float* __restrict__ sp_bias,
    float*       __restrict__ out)
{
    __shared__ float4 s_embed[DD / 4];

    const int b      = blockIdx.x;
    const int bucket = blockIdx.y;

    const float4* erow = reinterpret_cast<const float4*>(embed + (size_t)b * DD);
    for (int i = threadIdx.x; i < DD / 4; i += blockDim.x)
        s_embed[i] = erow[i];
    __syncthreads();

    const int warp = threadIdx.x >> 5;
    const int lane = threadIdx.x & 31;

    const int begin = g_off[b * (NB + 1) + bucket];
    const int end   = g_off[b * (NB + 1) + bucket + 1];
    const unsigned int* items = g_items + (size_t)b * KK;

    for (int j = begin + warp; j < end; j += 8) {
        const unsigned int it  = items[j];
        const int          k   = (int)(it & 1023u);
        const long long    idx = (long long)(it >> 10);

        const float4* wrow =
            reinterpret_cast<const float4*>(sp_weight + idx * DD);

        float sum = 0.0f;
        #pragma unroll
        for (int i = 0; i < DD / 128; ++i) {       // 4 independent LDG.128
            float4 w = wrow[i * 32 + lane];
            float4 e = s_embed[i * 32 + lane];
            sum = fmaf(w.x, e.x, sum);
            sum = fmaf(w.y, e.y, sum);
            sum = fmaf(w.z, e.z, sum);
            sum = fmaf(w.w, e.w, sum);
        }

        #pragma unroll
        for (int off = 16; off; off >>= 1)
            sum += __shfl_xor_sync(0xffffffffu, sum, off);

        if (lane == 0)
            out[b * KK + k] = sum + __ldg(&sp_bias[idx]);
    }
}

extern "C" void kernel_launch(void* const* d_in, const int* in_sizes, int n_in,
                              void* d_out, int out_size) {
    const float* embed     = (const float*)d_in[0];
    const int*   shortlist = (const int*)  d_in[1];
    const float* sp_weight = (const float*)d_in[2];
    const float* sp_bias   = (const float*)d_in[3];
    float*       out       = (float*)d_out;

    bucket_kernel<<<BB, 256>>>(shortlist);
    dot_kernel<<<dim3(BB, NB), 256>>>(embed, sp_weight, sp_bias, out);
}